// round 14
// baseline (speedup 1.0000x reference)
#include <cuda_runtime.h>
#include <cstdint>

// Blur_82471962018173: depthwise 4x4 FIR on (4,128,513,513) fp32 -> (4,128,512,512)
// Separable: w_j = k[0][j], u_i = k[i][0]/k[0][0] (exact: rank-1 dyadic kernel).
//
// R12: persistent CTAs + cross-tile double buffering. R11's split-wait was
// neutral -> intra-CTA overlap isn't the binder. Hypothesis: per-CTA cold-start
// DRAM stalls (16384 CTAs x full memory latency, 28 waves). Here 592 CTAs each
// walk ~28 tiles; tile t+1 is cp.async-staged into the alternate 39KB buffer
// while tile t computes, so only the CTA's FIRST tile pays cold latency.
// Addressing identical to R9/R11 (absolute-offset flat 16B cp.async; no %RING,
// no 4B copies -> avoids the R10 issue-bound regression).

#define W_IN  513
#define H_IN  513
#define W_OUT 512
#define H_OUT 512
#define TILE_ROWS 16
#define IN_ROWS   (TILE_ROWS + 3)          // 19 staged input rows
#define STAGE_FLOATS (IN_ROWS * W_IN)      // 9747
#define BUFSZ 9756                         // floats; padded so buf1 is 16B aligned
#define NT 512
#define GRID_CTAS 592                      // 4 per SM queued, 2 resident

__global__ __launch_bounds__(NT, 2)
void blur_persist_kernel(const float* __restrict__ in,
                         const float* __restrict__ kern,
                         float* __restrict__ out,
                         int total_tiles)
{
    extern __shared__ __align__(16) float smem_all[];   // 2 * BUFSZ floats
    float* buf0 = smem_all;
    float* buf1 = smem_all + BUFSZ;

    const int tid = threadIdx.x;

    // Separable factorization (uniform across threads)
    const float w0 = __ldg(kern + 0);
    const float w1 = __ldg(kern + 1);
    const float w2 = __ldg(kern + 2);
    const float w3 = __ldg(kern + 3);
    const float inv = 1.0f / w0;
    const float u1 = __ldg(kern + 4)  * inv;
    const float u2 = __ldg(kern + 8)  * inv;
    const float u3 = __ldg(kern + 12) * inv;   // u0 == 1

    // Stage [lo,hi) absolute flat range into sm (scalar head/tail <=3 floats,
    // 16B cp.async interior), one commit_group per call.
    auto stage_range = [&](float* sm, long aorg, int shift, long lo, long hi) {
        const long a0 = (lo + 3) & ~3L;
        const long a1 = hi & ~3L;
        for (long f = lo + tid; f < a0; f += NT)
            sm[(int)(f - aorg) + shift] = __ldg(in + f);
        for (long f = a1 + tid; f < hi; f += NT)
            sm[(int)(f - aorg) + shift] = __ldg(in + f);
        const unsigned int n4 = (unsigned int)((a1 - a0) >> 2);
        const float4* __restrict__ gsrc = reinterpret_cast<const float4*>(in + a0);
        const unsigned int sbase =
            (unsigned int)__cvta_generic_to_shared(sm + ((int)(a0 - aorg) + shift));
        for (unsigned int i = (unsigned int)tid; i < n4; i += NT) {
            asm volatile("cp.async.cg.shared.global [%0], [%1], 16;\n"
                         :: "r"(sbase + i * 16u), "l"(gsrc + i));
        }
        asm volatile("cp.async.commit_group;\n" ::: "memory");
    };

    // Issue full staging (2 commit groups) for tile tau into sm.
    auto stage_tile = [&](int tau, float* sm) {
        const int  img = tau >> 5;                    // 32 tiles per image
        const int  y0  = (tau & 31) * TILE_ROWS;
        const long gbase = (long)img * (W_IN * H_IN);
        const long aorg  = gbase + (long)(y0 - 1) * W_IN;      // may be negative
        const int  shift = (int)(((aorg % 4) + 4) & 3);
        const int  v_lo = (y0 - 1 < 0) ? 0 : (y0 - 1);
        const int  v_hi = (y0 + IN_ROWS - 1 < H_IN) ? (y0 + IN_ROWS - 1) : H_IN;
        const long aflat_lo = gbase + (long)v_lo * W_IN;
        const long aflat_hi = gbase + (long)v_hi * W_IN;
        const long amid     = gbase + (long)(y0 + 10) * W_IN;  // A/B split
        const int  s_lo = (int)(aflat_lo - aorg) + shift;
        const int  s_hi = (int)(aflat_hi - aorg) + shift;
        // zero-pad head/tail (nonempty only at image top/bottom tiles)
        for (int i = tid; i < s_lo; i += NT) sm[i] = 0.f;
        for (int i = s_hi + tid; i < STAGE_FLOATS + shift; i += NT) sm[i] = 0.f;
        stage_range(sm, aorg, shift, aflat_lo, amid);
        stage_range(sm, aorg, shift, amid, aflat_hi);
    };

    // Compute the 16 output rows of tile tau from staged buffer sm.
    const int x = tid;
    const bool lok = (x > 0);
    const bool rok = (x < W_OUT - 1);
    auto compute_tile = [&](int tau, const float* sm) {
        const int  img = tau >> 5;
        const int  y0  = (tau & 31) * TILE_ROWS;
        const long aorg = (long)img * (W_IN * H_IN) + (long)(y0 - 1) * W_IN;
        const int  shift = (int)(((aorg % 4) + 4) & 3);
        const float* __restrict__ sb = sm + shift + x;

        auto hrow = [&](int lr) -> float {
            const float* __restrict__ row = sb + lr * W_IN;
            const float a0 = lok ? row[-1] : 0.f;
            const float a1 = row[0];
            const float a2 = row[1];
            const float a3 = rok ? row[2] : 0.f;
            return fmaf(w0, a0, fmaf(w1, a1, fmaf(w2, a2, w3 * a3)));
        };

        float h0 = hrow(0);
        float h1 = hrow(1);
        float h2 = hrow(2);
        float* __restrict__ orow =
            out + (size_t)img * (W_OUT * H_OUT) + (size_t)y0 * W_OUT + x;
        #pragma unroll
        for (int r = 0; r < TILE_ROWS; ++r) {
            const float h3 = hrow(r + 3);
            float o = fmaf(u1, h1, h0);
            o = fmaf(u2, h2, o);
            o = fmaf(u3, h3, o);
            orow[(size_t)r * W_OUT] = o;
            h0 = h1; h1 = h2; h2 = h3;
        }
    };

    // ---- Pipelined tile walk: tau, tau+grid, tau+2*grid, ...
    int tau = blockIdx.x;
    if (tau >= total_tiles) return;

    float* cur = buf0;
    float* nxt = buf1;
    stage_tile(tau, cur);                       // prologue: 2 groups in flight

    for (;;) {
        const int tau_next = tau + GRID_CTAS;
        const bool have_next = (tau_next < total_tiles);
        if (have_next) {
            stage_tile(tau_next, nxt);          // 2 more groups (4 pending)
            asm volatile("cp.async.wait_group 2;\n" ::: "memory");  // cur done
        } else {
            asm volatile("cp.async.wait_group 0;\n" ::: "memory");
        }
        __syncthreads();                        // staged data + zero STS visible

        compute_tile(tau, cur);

        __syncthreads();                        // all reads of `cur` done before
                                                // it is overwritten next iter
        if (!have_next) break;
        tau = tau_next;
        float* t = cur; cur = nxt; nxt = t;
    }
}

extern "C" void kernel_launch(void* const* d_in, const int* in_sizes, int n_in,
                              void* d_out, int out_size)
{
    (void)n_in; (void)out_size;
    const float* input  = (const float*)d_in[0];
    const float* kernel = (const float*)d_in[1];
    float*       output = (float*)d_out;

    const int n_images   = in_sizes[0] / (W_IN * H_IN);   // N*C = 512
    const int total_tiles = n_images * (H_OUT / TILE_ROWS);

    const int smem_bytes = 2 * BUFSZ * (int)sizeof(float);   // 78048
    cudaFuncSetAttribute(blur_persist_kernel,
                         cudaFuncAttributeMaxDynamicSharedMemorySize, smem_bytes);

    blur_persist_kernel<<<GRID_CTAS, NT, smem_bytes>>>(input, kernel, output,
                                                       total_tiles);
}